// round 1
// baseline (speedup 1.0000x reference)
#include <cuda_runtime.h>
#include <cuda_bf16.h>
#include <cstdint>

#define N_NODES 50000
#define N_EDGES 800000
#define D 512

// Scratch for intermediate h = u_f @ W  (50000 x 512 fp32 = 102.4 MB)
__device__ float g_h[(size_t)N_NODES * D];

// ---------------------------------------------------------------------------
// Dense GEMM: h[N_NODES, D] = A[N_NODES, D] * B[D, D]   (all row-major fp32)
// Block tile 128x64, K-tile 16, 256 threads, 8x4 register micro-tile.
// ---------------------------------------------------------------------------
#define BM 128
#define BN 64
#define BK 16
#define TM 8
#define TN 4

__global__ __launch_bounds__(256) void gemm_kernel(const float* __restrict__ A,
                                                   const float* __restrict__ B,
                                                   float* __restrict__ C) {
    __shared__ float As[BK][BM];      // transposed A tile
    __shared__ float Bs[BK][BN];

    const int tid = threadIdx.x;
    const int ty = tid >> 4;          // 0..15 -> row group
    const int tx = tid & 15;          // 0..15 -> col group
    const int blockRow = blockIdx.y * BM;
    const int blockCol = blockIdx.x * BN;

    // loader mapping
    const int arow = tid >> 1;            // 0..127
    const int acol = (tid & 1) * 8;       // 0 or 8
    const int brow = tid >> 4;            // 0..15
    const int bcol = (tid & 15) * 4;      // 0..60

    float acc[TM][TN];
#pragma unroll
    for (int i = 0; i < TM; i++)
#pragma unroll
        for (int j = 0; j < TN; j++) acc[i][j] = 0.0f;

    const int gr = blockRow + arow;
    const bool a_ok = (gr < N_NODES);

    for (int k0 = 0; k0 < D; k0 += BK) {
        // --- load A tile (128x16), store transposed ---
        float4 a0 = make_float4(0.f, 0.f, 0.f, 0.f);
        float4 a1 = a0;
        if (a_ok) {
            const float4* ap = reinterpret_cast<const float4*>(A + (size_t)gr * D + k0 + acol);
            a0 = ap[0];
            a1 = ap[1];
        }
        As[acol + 0][arow] = a0.x;
        As[acol + 1][arow] = a0.y;
        As[acol + 2][arow] = a0.z;
        As[acol + 3][arow] = a0.w;
        As[acol + 4][arow] = a1.x;
        As[acol + 5][arow] = a1.y;
        As[acol + 6][arow] = a1.z;
        As[acol + 7][arow] = a1.w;

        // --- load B tile (16x64) ---
        const float4 b = *reinterpret_cast<const float4*>(B + (size_t)(k0 + brow) * D + blockCol + bcol);
        *reinterpret_cast<float4*>(&Bs[brow][bcol]) = b;

        __syncthreads();

#pragma unroll
        for (int k = 0; k < BK; k++) {
            float4 ra0 = *reinterpret_cast<const float4*>(&As[k][ty * TM]);
            float4 ra1 = *reinterpret_cast<const float4*>(&As[k][ty * TM + 4]);
            float4 rb  = *reinterpret_cast<const float4*>(&Bs[k][tx * TN]);
            float ra[TM] = {ra0.x, ra0.y, ra0.z, ra0.w, ra1.x, ra1.y, ra1.z, ra1.w};
            float rbv[TN] = {rb.x, rb.y, rb.z, rb.w};
#pragma unroll
            for (int i = 0; i < TM; i++)
#pragma unroll
                for (int j = 0; j < TN; j++)
                    acc[i][j] = fmaf(ra[i], rbv[j], acc[i][j]);
        }
        __syncthreads();
    }

    // --- store ---
#pragma unroll
    for (int i = 0; i < TM; i++) {
        const int r = blockRow + ty * TM + i;
        if (r < N_NODES) {
            float4 v = make_float4(acc[i][0], acc[i][1], acc[i][2], acc[i][3]);
            *reinterpret_cast<float4*>(C + (size_t)r * D + blockCol + tx * TN) = v;
        }
    }
}

// ---------------------------------------------------------------------------
// SpMM + ReLU: out[r,:] = relu( sum_{e: rows[e]==r} vals[e] * h[cols[e],:] )
// adj_rows is sorted -> one warp per output row, binary-search the edge range,
// accumulate 512 dims in 4 float4 per lane. No atomics.
// ---------------------------------------------------------------------------
__global__ __launch_bounds__(256) void spmm_relu_kernel(const int* __restrict__ rows,
                                                        const int* __restrict__ cols,
                                                        const float* __restrict__ vals,
                                                        const float* __restrict__ h,
                                                        float* __restrict__ out) {
    const int warp = threadIdx.x >> 5;
    const int lane = threadIdx.x & 31;
    const int r = blockIdx.x * (blockDim.x >> 5) + warp;
    if (r >= N_NODES) return;

    // lower_bound(rows, r)
    int lo = 0, hi = N_EDGES;
    while (lo < hi) {
        int mid = (lo + hi) >> 1;
        if (__ldg(&rows[mid]) < r) lo = mid + 1; else hi = mid;
    }
    const int start = lo;
    // upper_bound(rows, r)
    hi = N_EDGES;
    while (lo < hi) {
        int mid = (lo + hi) >> 1;
        if (__ldg(&rows[mid]) <= r) lo = mid + 1; else hi = mid;
    }
    const int end = lo;

    float4 acc[4];
#pragma unroll
    for (int j = 0; j < 4; j++) acc[j] = make_float4(0.f, 0.f, 0.f, 0.f);

    for (int e = start; e < end; e++) {
        const float v = __ldg(&vals[e]);
        const int c = __ldg(&cols[e]);
        const float4* hp = reinterpret_cast<const float4*>(h + (size_t)c * D);
#pragma unroll
        for (int j = 0; j < 4; j++) {
            float4 t = __ldg(&hp[lane + 32 * j]);
            acc[j].x = fmaf(v, t.x, acc[j].x);
            acc[j].y = fmaf(v, t.y, acc[j].y);
            acc[j].z = fmaf(v, t.z, acc[j].z);
            acc[j].w = fmaf(v, t.w, acc[j].w);
        }
    }

    float4* op = reinterpret_cast<float4*>(out + (size_t)r * D);
#pragma unroll
    for (int j = 0; j < 4; j++) {
        float4 a = acc[j];
        a.x = fmaxf(a.x, 0.f);
        a.y = fmaxf(a.y, 0.f);
        a.z = fmaxf(a.z, 0.f);
        a.w = fmaxf(a.w, 0.f);
        op[lane + 32 * j] = a;
    }
}

// ---------------------------------------------------------------------------
// kernel_launch
// Inputs (metadata order): adj_rows[i32, 800000], adj_cols[i32, 800000],
//                          adj_vals[f32, 800000], u_f[f32, 50000*512],
//                          weight[f32, 512*512]
// Output: f32 [50000, 512]
// ---------------------------------------------------------------------------
extern "C" void kernel_launch(void* const* d_in, const int* in_sizes, int n_in,
                              void* d_out, int out_size) {
    const int* adj_rows = (const int*)d_in[0];
    const int* adj_cols = (const int*)d_in[1];
    const float* adj_vals = (const float*)d_in[2];
    const float* u_f = (const float*)d_in[3];
    const float* weight = (const float*)d_in[4];
    float* out = (float*)d_out;

    float* h;
    cudaGetSymbolAddress((void**)&h, g_h);

    dim3 ggrid(D / BN, (N_NODES + BM - 1) / BM);
    gemm_kernel<<<ggrid, 256>>>(u_f, weight, h);

    const int warps_per_block = 8;
    const int nblocks = (N_NODES + warps_per_block - 1) / warps_per_block;
    spmm_relu_kernel<<<nblocks, 256>>>(adj_rows, adj_cols, adj_vals, h, out);
}

// round 3
// speedup vs baseline: 1.8875x; 1.8875x over previous
#include <cuda_runtime.h>
#include <cuda_bf16.h>
#include <cstdint>

#define N_NODES 50000
#define N_EDGES 800000
#define D 512
#define M_PAD 50048            // 391 * 128

// ---------------------------------------------------------------------------
// Device scratch (no allocations allowed)
// ---------------------------------------------------------------------------
__device__ float g_h[(size_t)M_PAD * D];                 // GEMM output (padded)
__device__ __nv_bfloat16 g_Ahi[(size_t)M_PAD * D];
__device__ __nv_bfloat16 g_Alo[(size_t)M_PAD * D];
__device__ __nv_bfloat16 g_Bthi[(size_t)D * D];          // weight^T hi  [n][k]
__device__ __nv_bfloat16 g_Btlo[(size_t)D * D];          // weight^T lo  [n][k]

// ---------------------------------------------------------------------------
// helpers
// ---------------------------------------------------------------------------
__device__ __forceinline__ uint32_t smem_to_u32(const void* p) {
    uint32_t a;
    asm("{ .reg .u64 t; cvta.to.shared.u64 t, %1; cvt.u32.u64 %0, t; }" : "=r"(a) : "l"(p));
    return a;
}
__device__ __forceinline__ uint32_t swz128(uint32_t o) { return o ^ ((o >> 3) & 0x70); }

__device__ __forceinline__ void cp_async16(uint32_t saddr, const void* gptr) {
    asm volatile("cp.async.cg.shared.global [%0], [%1], 16;" :: "r"(saddr), "l"(gptr));
}
#define CP_COMMIT() asm volatile("cp.async.commit_group;" ::: "memory")
#define CP_WAIT(n) asm volatile("cp.async.wait_group %0;" :: "n"(n) : "memory")

__device__ __forceinline__ void ldsm4(uint32_t r[4], uint32_t addr) {
    asm volatile("ldmatrix.sync.aligned.m8n8.x4.shared.b16 {%0,%1,%2,%3}, [%4];"
                 : "=r"(r[0]), "=r"(r[1]), "=r"(r[2]), "=r"(r[3]) : "r"(addr));
}
__device__ __forceinline__ void mma16816(float c[4], const uint32_t a[4], const uint32_t b[2]) {
    asm volatile("mma.sync.aligned.m16n8k16.row.col.f32.bf16.bf16.f32 "
                 "{%0,%1,%2,%3}, {%4,%5,%6,%7}, {%8,%9}, {%0,%1,%2,%3};"
                 : "+f"(c[0]), "+f"(c[1]), "+f"(c[2]), "+f"(c[3])
                 : "r"(a[0]), "r"(a[1]), "r"(a[2]), "r"(a[3]), "r"(b[0]), "r"(b[1]));
}

// ---------------------------------------------------------------------------
// Split-convert kernels
// ---------------------------------------------------------------------------
__global__ __launch_bounds__(256) void convertA_kernel(const float* __restrict__ A,
                                                       __nv_bfloat16* __restrict__ Ahi,
                                                       __nv_bfloat16* __restrict__ Alo) {
    const size_t i4 = (size_t)blockIdx.x * blockDim.x + threadIdx.x;
    const size_t total4 = (size_t)M_PAD * D / 4;
    if (i4 >= total4) return;
    const size_t elem = i4 * 4;
    const size_t row = elem >> 9;
    float4 v = make_float4(0.f, 0.f, 0.f, 0.f);
    if (row < N_NODES) v = *reinterpret_cast<const float4*>(A + elem);
    float f[4] = {v.x, v.y, v.z, v.w};
    __nv_bfloat16 hi[4], lo[4];
#pragma unroll
    for (int j = 0; j < 4; j++) {
        hi[j] = __float2bfloat16_rn(f[j]);
        lo[j] = __float2bfloat16_rn(f[j] - __bfloat162float(hi[j]));
    }
    __nv_bfloat162* ph = reinterpret_cast<__nv_bfloat162*>(Ahi + elem);
    __nv_bfloat162* pl = reinterpret_cast<__nv_bfloat162*>(Alo + elem);
    ph[0] = __nv_bfloat162(hi[0], hi[1]);
    ph[1] = __nv_bfloat162(hi[2], hi[3]);
    pl[0] = __nv_bfloat162(lo[0], lo[1]);
    pl[1] = __nv_bfloat162(lo[2], lo[3]);
}

// weight [k][n] row-major -> Bt[n][k] split into hi/lo
__global__ void convertW_kernel(const float* __restrict__ W,
                                __nv_bfloat16* __restrict__ Bth,
                                __nv_bfloat16* __restrict__ Btl) {
    __shared__ float tile[32][33];
    const int k = blockIdx.y * 32 + threadIdx.y;
    const int n = blockIdx.x * 32 + threadIdx.x;
    tile[threadIdx.y][threadIdx.x] = W[(size_t)k * D + n];
    __syncthreads();
    const int no = blockIdx.x * 32 + threadIdx.y;
    const int ko = blockIdx.y * 32 + threadIdx.x;
    const float x = tile[threadIdx.x][threadIdx.y];
    const __nv_bfloat16 hi = __float2bfloat16_rn(x);
    const __nv_bfloat16 lo = __float2bfloat16_rn(x - __bfloat162float(hi));
    Bth[(size_t)no * D + ko] = hi;
    Btl[(size_t)no * D + ko] = lo;
}

// ---------------------------------------------------------------------------
// HMMA (mma.sync bf16) split GEMM: h[M_PAD,512] = A @ W
// CTA tile 128x128, K chunk 64, 3-stage cp.async, SW128 smem, 8 warps (4m x 2n),
// warp tile 32x64. 3 MMAs per logical mma (hi*hi + hi*lo + lo*hi).
// ---------------------------------------------------------------------------
#define TILE_M 128
#define TILE_N 128
#define BKC 64
#define N_CHUNKS (D / BKC)     // 8
#define NSTAGE 3
// per-stage smem: 4 tiles of 128x64 bf16 (16 KB each)
#define A_HI_OFF 0
#define A_LO_OFF 16384
#define B_HI_OFF 32768
#define B_LO_OFF 49152
#define STAGE_BYTES 65536
#define GEMM_SMEM (NSTAGE * STAGE_BYTES)   // 192 KB

__device__ __forceinline__ void load_chunk(uint32_t sbase,
                                           const __nv_bfloat16* __restrict__ Ah,
                                           const __nv_bfloat16* __restrict__ Al,
                                           const __nv_bfloat16* __restrict__ Bh,
                                           const __nv_bfloat16* __restrict__ Bl,
                                           int mrow0, int nrow0, int k0, int tid) {
#pragma unroll
    for (int t = 0; t < 4; t++) {
        const int idx = t * 256 + tid;
        const int row = idx >> 3;
        const int c16 = idx & 7;
        const uint32_t soff = swz128((uint32_t)(row * 128 + c16 * 16));
        const size_t ga = (size_t)(mrow0 + row) * D + k0 + c16 * 8;
        const size_t gb = (size_t)(nrow0 + row) * D + k0 + c16 * 8;
        cp_async16(sbase + A_HI_OFF + soff, Ah + ga);
        cp_async16(sbase + A_LO_OFF + soff, Al + ga);
        cp_async16(sbase + B_HI_OFF + soff, Bh + gb);
        cp_async16(sbase + B_LO_OFF + soff, Bl + gb);
    }
    CP_COMMIT();
}

__global__ __launch_bounds__(256, 1) void gemm_mma_kernel(
    const __nv_bfloat16* __restrict__ Ah, const __nv_bfloat16* __restrict__ Al,
    const __nv_bfloat16* __restrict__ Bh, const __nv_bfloat16* __restrict__ Bl,
    float* __restrict__ C) {
    extern __shared__ char smem[];
    const uint32_t sb = smem_to_u32(smem);
    const int tid = threadIdx.x;
    const int wid = tid >> 5;
    const int lane = tid & 31;

    const int mrow0 = blockIdx.y * TILE_M;
    const int nrow0 = blockIdx.x * TILE_N;

    const int m0 = (wid & 3) * 32;   // warp m offset in tile
    const int n0 = (wid >> 2) * 64;  // warp n offset in tile

    float acc[2][8][4];
#pragma unroll
    for (int mt = 0; mt < 2; mt++)
#pragma unroll
        for (int nt = 0; nt < 8; nt++)
#pragma unroll
            for (int q = 0; q < 4; q++) acc[mt][nt][q] = 0.f;

    // prologue
    load_chunk(sb + 0 * STAGE_BYTES, Ah, Al, Bh, Bl, mrow0, nrow0, 0 * BKC, tid);
    load_chunk(sb + 1 * STAGE_BYTES, Ah, Al, Bh, Bl, mrow0, nrow0, 1 * BKC, tid);
    load_chunk(sb + 2 * STAGE_BYTES, Ah, Al, Bh, Bl, mrow0, nrow0, 2 * BKC, tid);

    // ldmatrix lane addressing (constant per thread)
    const int a_rowl = lane & 15;
    const int a_half = lane >> 4;          // 0/1 -> 16B col half
    const int b_g = lane >> 3;             // matrix group 0..3
    const int b_rowl = lane & 7;

    for (int c = 0; c < N_CHUNKS; c++) {
        if (c < N_CHUNKS - 2) { CP_WAIT(2); }
        else if (c == N_CHUNKS - 2) { CP_WAIT(1); }
        else { CP_WAIT(0); }
        __syncthreads();

        const uint32_t stage = sb + (uint32_t)(c % NSTAGE) * STAGE_BYTES;
        const uint32_t aHi = stage + A_HI_OFF, aLo = stage + A_LO_OFF;
        const uint32_t bHi = stage + B_HI_OFF, bLo = stage + B_LO_OFF;

#pragma unroll
        for (int ks = 0; ks < 4; ks++) {
            uint32_t ah[2][4], al[2][4];
#pragma unroll
            for (int mt = 0; mt < 2; mt++) {
                const uint32_t aoff = swz128((uint32_t)((m0 + mt * 16 + a_rowl) * 128 + ks * 32 + a_half * 16));
                ldsm4(ah[mt], aHi + aoff);
                ldsm4(al[mt], aLo + aoff);
            }
            uint32_t bh[8][2], bl[8][2];
#pragma unroll
            for (int jt = 0; jt < 4; jt++) {
                const int brow = n0 + (jt * 2 + (b_g >> 1)) * 8 + b_rowl;
                const int bkb = ks * 32 + (b_g & 1) * 16;
                const uint32_t boff = swz128((uint32_t)(brow * 128 + bkb));
                uint32_t t4[4];
                ldsm4(t4, bHi + boff);
                bh[jt * 2][0] = t4[0]; bh[jt * 2][1] = t4[1];
                bh[jt * 2 + 1][0] = t4[2]; bh[jt * 2 + 1][1] = t4[3];
                ldsm4(t4, bLo + boff);
                bl[jt * 2][0] = t4[0]; bl[jt * 2][1] = t4[1];
                bl[jt * 2 + 1][0] = t4[2]; bl[jt * 2 + 1][1] = t4[3];
            }
#pragma unroll
            for (int mt = 0; mt < 2; mt++)
#pragma unroll
                for (int nt = 0; nt < 8; nt++) {
                    mma16816(acc[mt][nt], ah[mt], bh[nt]);
                    mma16816(acc[mt][nt], ah[mt], bl[nt]);
                    mma16816(acc[mt][nt], al[mt], bh[nt]);
                }
        }
        __syncthreads();
        if (c + NSTAGE < N_CHUNKS)
            load_chunk(stage, Ah, Al, Bh, Bl, mrow0, nrow0, (c + NSTAGE) * BKC, tid);
    }

    // epilogue: direct stores (float2 per fragment half)
    const int er = lane >> 2;
    const int ec = (lane & 3) * 2;
#pragma unroll
    for (int mt = 0; mt < 2; mt++) {
        const int r0 = mrow0 + m0 + mt * 16 + er;
#pragma unroll
        for (int nt = 0; nt < 8; nt++) {
            const int col = nrow0 + n0 + nt * 8 + ec;
            *reinterpret_cast<float2*>(C + (size_t)r0 * D + col) =
                make_float2(acc[mt][nt][0], acc[mt][nt][1]);
            *reinterpret_cast<float2*>(C + (size_t)(r0 + 8) * D + col) =
                make_float2(acc[mt][nt][2], acc[mt][nt][3]);
        }
    }
}

// ---------------------------------------------------------------------------
// SpMM + ReLU: warp-per-row (rows sorted), 2x edge unroll for MLP
// ---------------------------------------------------------------------------
__global__ __launch_bounds__(256) void spmm_relu_kernel(const int* __restrict__ rows,
                                                        const int* __restrict__ cols,
                                                        const float* __restrict__ vals,
                                                        const float* __restrict__ h,
                                                        float* __restrict__ out) {
    const int warp = threadIdx.x >> 5;
    const int lane = threadIdx.x & 31;
    const int r = blockIdx.x * (blockDim.x >> 5) + warp;
    if (r >= N_NODES) return;

    int lo = 0, hi = N_EDGES;
    while (lo < hi) {
        int mid = (lo + hi) >> 1;
        if (__ldg(&rows[mid]) < r) lo = mid + 1; else hi = mid;
    }
    const int start = lo;
    hi = N_EDGES;
    while (lo < hi) {
        int mid = (lo + hi) >> 1;
        if (__ldg(&rows[mid]) <= r) lo = mid + 1; else hi = mid;
    }
    const int end = lo;

    float4 acc[4];
#pragma unroll
    for (int j = 0; j < 4; j++) acc[j] = make_float4(0.f, 0.f, 0.f, 0.f);

    int e = start;
    for (; e + 2 <= end; e += 2) {
        const float v0 = __ldg(&vals[e]);
        const float v1 = __ldg(&vals[e + 1]);
        const int c0 = __ldg(&cols[e]);
        const int c1 = __ldg(&cols[e + 1]);
        const float4* h0 = reinterpret_cast<const float4*>(h + (size_t)c0 * D);
        const float4* h1 = reinterpret_cast<const float4*>(h + (size_t)c1 * D);
        float4 t0[4], t1[4];
#pragma unroll
        for (int j = 0; j < 4; j++) t0[j] = __ldg(&h0[lane + 32 * j]);
#pragma unroll
        for (int j = 0; j < 4; j++) t1[j] = __ldg(&h1[lane + 32 * j]);
#pragma unroll
        for (int j = 0; j < 4; j++) {
            acc[j].x = fmaf(v0, t0[j].x, acc[j].x);
            acc[j].y = fmaf(v0, t0[j].y, acc[j].y);
            acc[j].z = fmaf(v0, t0[j].z, acc[j].z);
            acc[j].w = fmaf(v0, t0[j].w, acc[j].w);
            acc[j].x = fmaf(v1, t1[j].x, acc[j].x);
            acc[j].y = fmaf(v1, t1[j].y, acc[j].y);
            acc[j].z = fmaf(v1, t1[j].z, acc[j].z);
            acc[j].w = fmaf(v1, t1[j].w, acc[j].w);
        }
    }
    if (e < end) {
        const float v = __ldg(&vals[e]);
        const int c = __ldg(&cols[e]);
        const float4* hp = reinterpret_cast<const float4*>(h + (size_t)c * D);
#pragma unroll
        for (int j = 0; j < 4; j++) {
            float4 t = __ldg(&hp[lane + 32 * j]);
            acc[j].x = fmaf(v, t.x, acc[j].x);
            acc[j].y = fmaf(v, t.y, acc[j].y);
            acc[j].z = fmaf(v, t.z, acc[j].z);
            acc[j].w = fmaf(v, t.w, acc[j].w);
        }
    }

    float4* op = reinterpret_cast<float4*>(out + (size_t)r * D);
#pragma unroll
    for (int j = 0; j < 4; j++) {
        float4 a = acc[j];
        a.x = fmaxf(a.x, 0.f);
        a.y = fmaxf(a.y, 0.f);
        a.z = fmaxf(a.z, 0.f);
        a.w = fmaxf(a.w, 0.f);
        op[lane + 32 * j] = a;
    }
}

// ---------------------------------------------------------------------------
// kernel_launch
// ---------------------------------------------------------------------------
extern "C" void kernel_launch(void* const* d_in, const int* in_sizes, int n_in,
                              void* d_out, int out_size) {
    const int* adj_rows = (const int*)d_in[0];
    const int* adj_cols = (const int*)d_in[1];
    const float* adj_vals = (const float*)d_in[2];
    const float* u_f = (const float*)d_in[3];
    const float* weight = (const float*)d_in[4];
    float* out = (float*)d_out;

    float* h;          cudaGetSymbolAddress((void**)&h, g_h);
    __nv_bfloat16* Ah; cudaGetSymbolAddress((void**)&Ah, g_Ahi);
    __nv_bfloat16* Al; cudaGetSymbolAddress((void**)&Al, g_Alo);
    __nv_bfloat16* Bh; cudaGetSymbolAddress((void**)&Bh, g_Bthi);
    __nv_bfloat16* Bl; cudaGetSymbolAddress((void**)&Bl, g_Btlo);

    cudaFuncSetAttribute(gemm_mma_kernel, cudaFuncAttributeMaxDynamicSharedMemorySize, GEMM_SMEM);

    const size_t total4 = (size_t)M_PAD * D / 4;
    convertA_kernel<<<(unsigned)((total4 + 255) / 256), 256>>>(u_f, Ah, Al);
    convertW_kernel<<<dim3(D / 32, D / 32), dim3(32, 32)>>>(weight, Bh, Bl);

    dim3 ggrid(D / TILE_N, M_PAD / TILE_M);   // (4, 391), x-fastest -> A tiles shared in L2
    gemm_mma_kernel<<<ggrid, 256, GEMM_SMEM>>>(Ah, Al, Bh, Bl, h);

    const int warps_per_block = 8;
    const int nblocks = (N_NODES + warps_per_block - 1) / warps_per_block;
    spmm_relu_kernel<<<nblocks, 256>>>(adj_rows, adj_cols, adj_vals, h, out);
}

// round 4
// speedup vs baseline: 2.3403x; 1.2399x over previous
#include <cuda_runtime.h>
#include <cuda_bf16.h>
#include <cuda_fp16.h>
#include <cstdint>

#define N_NODES 50000
#define N_EDGES 800000
#define D 512
#define M_PAD 50048            // 391 * 128

// ---------------------------------------------------------------------------
// Device scratch
// ---------------------------------------------------------------------------
__device__ __half g_h[(size_t)M_PAD * D];                // GEMM output, fp16 (51.2 MB)
__device__ __nv_bfloat16 g_Ahi[(size_t)M_PAD * D];
__device__ __nv_bfloat16 g_Alo[(size_t)M_PAD * D];
__device__ __nv_bfloat16 g_Bthi[(size_t)D * D];          // weight^T hi  [n][k]
__device__ __nv_bfloat16 g_Btlo[(size_t)D * D];          // weight^T lo  [n][k]
__device__ int g_rowptr[N_NODES + 1];

// ---------------------------------------------------------------------------
// helpers
// ---------------------------------------------------------------------------
__device__ __forceinline__ uint32_t smem_to_u32(const void* p) {
    uint32_t a;
    asm("{ .reg .u64 t; cvta.to.shared.u64 t, %1; cvt.u32.u64 %0, t; }" : "=r"(a) : "l"(p));
    return a;
}
__device__ __forceinline__ uint32_t swz128(uint32_t o) { return o ^ ((o >> 3) & 0x70); }

__device__ __forceinline__ void cp_async16(uint32_t saddr, const void* gptr) {
    asm volatile("cp.async.cg.shared.global [%0], [%1], 16;" :: "r"(saddr), "l"(gptr));
}
#define CP_COMMIT() asm volatile("cp.async.commit_group;" ::: "memory")
#define CP_WAIT(n) asm volatile("cp.async.wait_group %0;" :: "n"(n) : "memory")

__device__ __forceinline__ void ldsm4(uint32_t r[4], uint32_t addr) {
    asm volatile("ldmatrix.sync.aligned.m8n8.x4.shared.b16 {%0,%1,%2,%3}, [%4];"
                 : "=r"(r[0]), "=r"(r[1]), "=r"(r[2]), "=r"(r[3]) : "r"(addr));
}
__device__ __forceinline__ void mma16816(float c[4], const uint32_t a[4], const uint32_t b[2]) {
    asm volatile("mma.sync.aligned.m16n8k16.row.col.f32.bf16.bf16.f32 "
                 "{%0,%1,%2,%3}, {%4,%5,%6,%7}, {%8,%9}, {%0,%1,%2,%3};"
                 : "+f"(c[0]), "+f"(c[1]), "+f"(c[2]), "+f"(c[3])
                 : "r"(a[0]), "r"(a[1]), "r"(a[2]), "r"(a[3]), "r"(b[0]), "r"(b[1]));
}

// ---------------------------------------------------------------------------
// Split-convert kernels
// ---------------------------------------------------------------------------
__global__ __launch_bounds__(256) void convertA_kernel(const float* __restrict__ A,
                                                       __nv_bfloat16* __restrict__ Ahi,
                                                       __nv_bfloat16* __restrict__ Alo) {
    const size_t i4 = (size_t)blockIdx.x * blockDim.x + threadIdx.x;
    const size_t total4 = (size_t)M_PAD * D / 4;
    if (i4 >= total4) return;
    const size_t elem = i4 * 4;
    const size_t row = elem >> 9;
    float4 v = make_float4(0.f, 0.f, 0.f, 0.f);
    if (row < N_NODES) v = *reinterpret_cast<const float4*>(A + elem);
    float f[4] = {v.x, v.y, v.z, v.w};
    __nv_bfloat16 hi[4], lo[4];
#pragma unroll
    for (int j = 0; j < 4; j++) {
        hi[j] = __float2bfloat16_rn(f[j]);
        lo[j] = __float2bfloat16_rn(f[j] - __bfloat162float(hi[j]));
    }
    __nv_bfloat162* ph = reinterpret_cast<__nv_bfloat162*>(Ahi + elem);
    __nv_bfloat162* pl = reinterpret_cast<__nv_bfloat162*>(Alo + elem);
    ph[0] = __nv_bfloat162(hi[0], hi[1]);
    ph[1] = __nv_bfloat162(hi[2], hi[3]);
    pl[0] = __nv_bfloat162(lo[0], lo[1]);
    pl[1] = __nv_bfloat162(lo[2], lo[3]);
}

__global__ void convertW_kernel(const float* __restrict__ W,
                                __nv_bfloat16* __restrict__ Bth,
                                __nv_bfloat16* __restrict__ Btl) {
    __shared__ float tile[32][33];
    const int k = blockIdx.y * 32 + threadIdx.y;
    const int n = blockIdx.x * 32 + threadIdx.x;
    tile[threadIdx.y][threadIdx.x] = W[(size_t)k * D + n];
    __syncthreads();
    const int no = blockIdx.x * 32 + threadIdx.y;
    const int ko = blockIdx.y * 32 + threadIdx.x;
    const float x = tile[threadIdx.x][threadIdx.y];
    const __nv_bfloat16 hi = __float2bfloat16_rn(x);
    const __nv_bfloat16 lo = __float2bfloat16_rn(x - __bfloat162float(hi));
    Bth[(size_t)no * D + ko] = hi;
    Btl[(size_t)no * D + ko] = lo;
}

// CSR row pointers from sorted rows
__global__ __launch_bounds__(256) void build_rowptr_kernel(const int* __restrict__ rows,
                                                           int* __restrict__ row_ptr) {
    const int e = blockIdx.x * blockDim.x + threadIdx.x;
    if (e >= N_EDGES) return;
    const int r = rows[e];
    const int r_prev = (e == 0) ? -1 : rows[e - 1];
    for (int k = r_prev + 1; k <= r; k++) row_ptr[k] = e;
    if (e == N_EDGES - 1) {
        for (int k = r + 1; k <= N_NODES; k++) row_ptr[k] = N_EDGES;
    }
}

// ---------------------------------------------------------------------------
// HMMA split GEMM: h[M_PAD,512] = A @ W, fp16 output
// CTA tile 128x256, K chunk 64, 2-stage cp.async, SW128 smem,
// 8 warps (2m x 4n), warp tile 64x64.
// ---------------------------------------------------------------------------
#define TILE_M 128
#define TILE_N 256
#define BKC 64
#define N_CHUNKS (D / BKC)     // 8
#define NSTAGE 2
#define A_HI_OFF 0
#define A_LO_OFF 16384
#define B_HI_OFF 32768
#define B_LO_OFF 65536
#define STAGE_BYTES 98304
#define GEMM_SMEM (NSTAGE * STAGE_BYTES)   // 192 KB

__device__ __forceinline__ void load_chunk(uint32_t sbase,
                                           const __nv_bfloat16* __restrict__ Ah,
                                           const __nv_bfloat16* __restrict__ Al,
                                           const __nv_bfloat16* __restrict__ Bh,
                                           const __nv_bfloat16* __restrict__ Bl,
                                           int mrow0, int nrow0, int k0, int tid) {
#pragma unroll
    for (int t = 0; t < 4; t++) {          // A: 128 rows x 8 16B chunks
        const int idx = t * 256 + tid;
        const int row = idx >> 3;
        const int c16 = idx & 7;
        const uint32_t soff = swz128((uint32_t)(row * 128 + c16 * 16));
        const size_t ga = (size_t)(mrow0 + row) * D + k0 + c16 * 8;
        cp_async16(sbase + A_HI_OFF + soff, Ah + ga);
        cp_async16(sbase + A_LO_OFF + soff, Al + ga);
    }
#pragma unroll
    for (int t = 0; t < 8; t++) {          // B: 256 rows x 8 16B chunks
        const int idx = t * 256 + tid;
        const int row = idx >> 3;
        const int c16 = idx & 7;
        const uint32_t soff = swz128((uint32_t)(row * 128 + c16 * 16));
        const size_t gb = (size_t)(nrow0 + row) * D + k0 + c16 * 8;
        cp_async16(sbase + B_HI_OFF + soff, Bh + gb);
        cp_async16(sbase + B_LO_OFF + soff, Bl + gb);
    }
    CP_COMMIT();
}

__global__ __launch_bounds__(256, 1) void gemm_mma_kernel(
    const __nv_bfloat16* __restrict__ Ah, const __nv_bfloat16* __restrict__ Al,
    const __nv_bfloat16* __restrict__ Bh, const __nv_bfloat16* __restrict__ Bl,
    __half* __restrict__ C) {
    extern __shared__ char smem[];
    const uint32_t sb = smem_to_u32(smem);
    const int tid = threadIdx.x;
    const int wid = tid >> 5;
    const int lane = tid & 31;

    const int mrow0 = blockIdx.y * TILE_M;
    const int nrow0 = blockIdx.x * TILE_N;

    const int m0 = (wid & 1) * 64;    // warp m offset
    const int n0 = (wid >> 1) * 64;   // warp n offset

    float acc[4][8][4];
#pragma unroll
    for (int mt = 0; mt < 4; mt++)
#pragma unroll
        for (int nt = 0; nt < 8; nt++)
#pragma unroll
            for (int q = 0; q < 4; q++) acc[mt][nt][q] = 0.f;

    load_chunk(sb + 0 * STAGE_BYTES, Ah, Al, Bh, Bl, mrow0, nrow0, 0 * BKC, tid);
    load_chunk(sb + 1 * STAGE_BYTES, Ah, Al, Bh, Bl, mrow0, nrow0, 1 * BKC, tid);

    const int a_rowl = lane & 15;
    const int a_half = lane >> 4;
    const int b_g = lane >> 3;
    const int b_rowl = lane & 7;

    for (int c = 0; c < N_CHUNKS; c++) {
        if (c < N_CHUNKS - 1) { CP_WAIT(1); } else { CP_WAIT(0); }
        __syncthreads();

        const uint32_t stage = sb + (uint32_t)(c & 1) * STAGE_BYTES;
        const uint32_t aHi = stage + A_HI_OFF, aLo = stage + A_LO_OFF;
        const uint32_t bHi = stage + B_HI_OFF, bLo = stage + B_LO_OFF;

#pragma unroll
        for (int ks = 0; ks < 4; ks++) {
            uint32_t ah[4][4], al[4][4];
#pragma unroll
            for (int mt = 0; mt < 4; mt++) {
                const uint32_t aoff = swz128((uint32_t)((m0 + mt * 16 + a_rowl) * 128 + ks * 32 + a_half * 16));
                ldsm4(ah[mt], aHi + aoff);
                ldsm4(al[mt], aLo + aoff);
            }
            uint32_t bh[8][2], bl[8][2];
#pragma unroll
            for (int jt = 0; jt < 4; jt++) {
                const int brow = n0 + (jt * 2 + (b_g >> 1)) * 8 + b_rowl;
                const int bkb = ks * 32 + (b_g & 1) * 16;
                const uint32_t boff = swz128((uint32_t)(brow * 128 + bkb));
                uint32_t t4[4];
                ldsm4(t4, bHi + boff);
                bh[jt * 2][0] = t4[0]; bh[jt * 2][1] = t4[1];
                bh[jt * 2 + 1][0] = t4[2]; bh[jt * 2 + 1][1] = t4[3];
                ldsm4(t4, bLo + boff);
                bl[jt * 2][0] = t4[0]; bl[jt * 2][1] = t4[1];
                bl[jt * 2 + 1][0] = t4[2]; bl[jt * 2 + 1][1] = t4[3];
            }
#pragma unroll
            for (int mt = 0; mt < 4; mt++)
#pragma unroll
                for (int nt = 0; nt < 8; nt++) {
                    mma16816(acc[mt][nt], ah[mt], bh[nt]);
                    mma16816(acc[mt][nt], ah[mt], bl[nt]);
                    mma16816(acc[mt][nt], al[mt], bh[nt]);
                }
        }
        __syncthreads();
        if (c + NSTAGE < N_CHUNKS)
            load_chunk(stage, Ah, Al, Bh, Bl, mrow0, nrow0, (c + NSTAGE) * BKC, tid);
    }

    // epilogue: fp16 stores
    const int er = lane >> 2;
    const int ec = (lane & 3) * 2;
#pragma unroll
    for (int mt = 0; mt < 4; mt++) {
        const int r0 = mrow0 + m0 + mt * 16 + er;
#pragma unroll
        for (int nt = 0; nt < 8; nt++) {
            const int col = nrow0 + n0 + nt * 8 + ec;
            *reinterpret_cast<__half2*>(C + (size_t)r0 * D + col) =
                __floats2half2_rn(acc[mt][nt][0], acc[mt][nt][1]);
            *reinterpret_cast<__half2*>(C + (size_t)(r0 + 8) * D + col) =
                __floats2half2_rn(acc[mt][nt][2], acc[mt][nt][3]);
        }
    }
}

// ---------------------------------------------------------------------------
// SpMM + ReLU: fp16 gather, 2 warps per row (256 dims each), CSR row_ptr,
// 4-edge unroll. lane handles 8 dims = one 16B load per edge.
// ---------------------------------------------------------------------------
__device__ __forceinline__ void fma8(float acc[8], const uint4& q, float v) {
    const __half2* hp = reinterpret_cast<const __half2*>(&q);
#pragma unroll
    for (int j = 0; j < 4; j++) {
        float2 f = __half22float2(hp[j]);
        acc[j * 2 + 0] = fmaf(v, f.x, acc[j * 2 + 0]);
        acc[j * 2 + 1] = fmaf(v, f.y, acc[j * 2 + 1]);
    }
}

__global__ __launch_bounds__(256) void spmm_relu_kernel(const int* __restrict__ row_ptr,
                                                        const int* __restrict__ cols,
                                                        const float* __restrict__ vals,
                                                        const __half* __restrict__ h,
                                                        float* __restrict__ out) {
    const int warp = threadIdx.x >> 5;
    const int lane = threadIdx.x & 31;
    const int gw = blockIdx.x * (blockDim.x >> 5) + warp;   // global warp id
    const int r = gw >> 1;
    if (r >= N_NODES) return;
    const int doff = (gw & 1) * 256 + lane * 8;             // 8 dims per lane

    const int start = __ldg(&row_ptr[r]);
    const int end = __ldg(&row_ptr[r + 1]);

    float acc[8];
#pragma unroll
    for (int j = 0; j < 8; j++) acc[j] = 0.f;

    int e = start;
    for (; e + 4 <= end; e += 4) {
        const int c0 = __ldg(&cols[e]);
        const int c1 = __ldg(&cols[e + 1]);
        const int c2 = __ldg(&cols[e + 2]);
        const int c3 = __ldg(&cols[e + 3]);
        const float v0 = __ldg(&vals[e]);
        const float v1 = __ldg(&vals[e + 1]);
        const float v2 = __ldg(&vals[e + 2]);
        const float v3 = __ldg(&vals[e + 3]);
        const uint4 q0 = *reinterpret_cast<const uint4*>(h + (size_t)c0 * D + doff);
        const uint4 q1 = *reinterpret_cast<const uint4*>(h + (size_t)c1 * D + doff);
        const uint4 q2 = *reinterpret_cast<const uint4*>(h + (size_t)c2 * D + doff);
        const uint4 q3 = *reinterpret_cast<const uint4*>(h + (size_t)c3 * D + doff);
        fma8(acc, q0, v0);
        fma8(acc, q1, v1);
        fma8(acc, q2, v2);
        fma8(acc, q3, v3);
    }
    for (; e < end; e++) {
        const int c = __ldg(&cols[e]);
        const float v = __ldg(&vals[e]);
        const uint4 q = *reinterpret_cast<const uint4*>(h + (size_t)c * D + doff);
        fma8(acc, q, v);
    }

    float4* op = reinterpret_cast<float4*>(out + (size_t)r * D + doff);
    op[0] = make_float4(fmaxf(acc[0], 0.f), fmaxf(acc[1], 0.f),
                        fmaxf(acc[2], 0.f), fmaxf(acc[3], 0.f));
    op[1] = make_float4(fmaxf(acc[4], 0.f), fmaxf(acc[5], 0.f),
                        fmaxf(acc[6], 0.f), fmaxf(acc[7], 0.f));
}

// ---------------------------------------------------------------------------
// kernel_launch
// ---------------------------------------------------------------------------
extern "C" void kernel_launch(void* const* d_in, const int* in_sizes, int n_in,
                              void* d_out, int out_size) {
    const int* adj_rows = (const int*)d_in[0];
    const int* adj_cols = (const int*)d_in[1];
    const float* adj_vals = (const float*)d_in[2];
    const float* u_f = (const float*)d_in[3];
    const float* weight = (const float*)d_in[4];
    float* out = (float*)d_out;

    __half* h;         cudaGetSymbolAddress((void**)&h, g_h);
    __nv_bfloat16* Ah; cudaGetSymbolAddress((void**)&Ah, g_Ahi);
    __nv_bfloat16* Al; cudaGetSymbolAddress((void**)&Al, g_Alo);
    __nv_bfloat16* Bh; cudaGetSymbolAddress((void**)&Bh, g_Bthi);
    __nv_bfloat16* Bl; cudaGetSymbolAddress((void**)&Bl, g_Btlo);
    int* rp;           cudaGetSymbolAddress((void**)&rp, g_rowptr);

    cudaFuncSetAttribute(gemm_mma_kernel, cudaFuncAttributeMaxDynamicSharedMemorySize, GEMM_SMEM);

    const size_t total4 = (size_t)M_PAD * D / 4;
    convertA_kernel<<<(unsigned)((total4 + 255) / 256), 256>>>(u_f, Ah, Al);
    convertW_kernel<<<dim3(D / 32, D / 32), dim3(32, 32)>>>(weight, Bh, Bl);
    build_rowptr_kernel<<<(N_EDGES + 255) / 256, 256>>>(adj_rows, rp);

    dim3 ggrid(D / TILE_N, M_PAD / TILE_M);   // (2, 391)
    gemm_mma_kernel<<<ggrid, 256, GEMM_SMEM>>>(Ah, Al, Bh, Bl, h);

    // 2 warps per row, 8 warps per block
    const int total_warps = N_NODES * 2;
    const int nblocks = (total_warps + 7) / 8;
    spmm_relu_kernel<<<nblocks, 256>>>(rp, adj_cols, adj_vals, h, out);
}

// round 5
// speedup vs baseline: 3.9517x; 1.6885x over previous
#include <cuda_runtime.h>
#include <cuda_bf16.h>
#include <cuda_fp16.h>
#include <cstdint>

#define N_NODES 50000
#define N_EDGES 800000
#define D 512
#define M_PAD 50048            // 391 * 128

// ---------------------------------------------------------------------------
// Device scratch
// ---------------------------------------------------------------------------
__device__ __half g_h[(size_t)M_PAD * D];                // GEMM output, fp16 (51.2 MB)
__device__ __half g_Af[(size_t)M_PAD * D];               // A in fp16 (51.2 MB)
__device__ __half g_Btf[(size_t)D * D];                  // weight^T fp16 [n][k]
__device__ int g_rowptr[N_NODES + 1];

// ---------------------------------------------------------------------------
// helpers
// ---------------------------------------------------------------------------
__device__ __forceinline__ uint32_t smem_to_u32(const void* p) {
    uint32_t a;
    asm("{ .reg .u64 t; cvta.to.shared.u64 t, %1; cvt.u32.u64 %0, t; }" : "=r"(a) : "l"(p));
    return a;
}
__device__ __forceinline__ uint32_t swz128(uint32_t o) { return o ^ ((o >> 3) & 0x70); }

__device__ __forceinline__ void cp_async16(uint32_t saddr, const void* gptr) {
    asm volatile("cp.async.cg.shared.global [%0], [%1], 16;" :: "r"(saddr), "l"(gptr));
}
#define CP_COMMIT() asm volatile("cp.async.commit_group;" ::: "memory")
#define CP_WAIT(n) asm volatile("cp.async.wait_group %0;" :: "n"(n) : "memory")

__device__ __forceinline__ void ldsm4(uint32_t r[4], uint32_t addr) {
    asm volatile("ldmatrix.sync.aligned.m8n8.x4.shared.b16 {%0,%1,%2,%3}, [%4];"
                 : "=r"(r[0]), "=r"(r[1]), "=r"(r[2]), "=r"(r[3]) : "r"(addr));
}
__device__ __forceinline__ void mma16816h(float c[4], const uint32_t a[4], const uint32_t b[2]) {
    asm volatile("mma.sync.aligned.m16n8k16.row.col.f32.f16.f16.f32 "
                 "{%0,%1,%2,%3}, {%4,%5,%6,%7}, {%8,%9}, {%0,%1,%2,%3};"
                 : "+f"(c[0]), "+f"(c[1]), "+f"(c[2]), "+f"(c[3])
                 : "r"(a[0]), "r"(a[1]), "r"(a[2]), "r"(a[3]), "r"(b[0]), "r"(b[1]));
}

// ---------------------------------------------------------------------------
// Convert kernels (fp32 -> fp16)
// ---------------------------------------------------------------------------
__global__ __launch_bounds__(256) void convertA_kernel(const float* __restrict__ A,
                                                       __half* __restrict__ Af) {
    const size_t i4 = (size_t)blockIdx.x * blockDim.x + threadIdx.x;
    const size_t total4 = (size_t)M_PAD * D / 4;
    if (i4 >= total4) return;
    const size_t elem = i4 * 4;
    const size_t row = elem >> 9;
    float4 v = make_float4(0.f, 0.f, 0.f, 0.f);
    if (row < N_NODES) v = *reinterpret_cast<const float4*>(A + elem);
    __half2* p = reinterpret_cast<__half2*>(Af + elem);
    p[0] = __floats2half2_rn(v.x, v.y);
    p[1] = __floats2half2_rn(v.z, v.w);
}

// weight [k][n] row-major -> Bt[n][k] fp16
__global__ void convertW_kernel(const float* __restrict__ W, __half* __restrict__ Bt) {
    __shared__ float tile[32][33];
    const int k = blockIdx.y * 32 + threadIdx.y;
    const int n = blockIdx.x * 32 + threadIdx.x;
    tile[threadIdx.y][threadIdx.x] = W[(size_t)k * D + n];
    __syncthreads();
    const int no = blockIdx.x * 32 + threadIdx.y;
    const int ko = blockIdx.y * 32 + threadIdx.x;
    Bt[(size_t)no * D + ko] = __float2half_rn(tile[threadIdx.x][threadIdx.y]);
}

// CSR row pointers from sorted rows
__global__ __launch_bounds__(256) void build_rowptr_kernel(const int* __restrict__ rows,
                                                           int* __restrict__ row_ptr) {
    const int e = blockIdx.x * blockDim.x + threadIdx.x;
    if (e >= N_EDGES) return;
    const int r = rows[e];
    const int r_prev = (e == 0) ? -1 : rows[e - 1];
    for (int k = r_prev + 1; k <= r; k++) row_ptr[k] = e;
    if (e == N_EDGES - 1) {
        for (int k = r + 1; k <= N_NODES; k++) row_ptr[k] = N_EDGES;
    }
}

// ---------------------------------------------------------------------------
// fp16 HMMA GEMM: h[M_PAD,512] = A @ W, fp16 in/out, fp32 accum
// CTA tile 128x128, K chunk 64, 3-stage cp.async, SW128 smem,
// 8 warps (4m x 2n), warp tile 32x64. 2 CTAs/SM.
// ---------------------------------------------------------------------------
#define TILE_M 128
#define TILE_N 128
#define BKC 64
#define N_CHUNKS (D / BKC)     // 8
#define NSTAGE 3
#define A_OFF 0
#define B_OFF 16384
#define STAGE_BYTES 32768
#define GEMM_SMEM (NSTAGE * STAGE_BYTES)   // 96 KB -> 2 CTAs/SM

__device__ __forceinline__ void load_chunk(uint32_t sbase,
                                           const __half* __restrict__ Af,
                                           const __half* __restrict__ Bt,
                                           int mrow0, int nrow0, int k0, int tid) {
#pragma unroll
    for (int t = 0; t < 4; t++) {          // A: 128 rows x 8 16B chunks
        const int idx = t * 256 + tid;
        const int row = idx >> 3;
        const int c16 = idx & 7;
        const uint32_t soff = swz128((uint32_t)(row * 128 + c16 * 16));
        cp_async16(sbase + A_OFF + soff, Af + (size_t)(mrow0 + row) * D + k0 + c16 * 8);
        cp_async16(sbase + B_OFF + soff, Bt + (size_t)(nrow0 + row) * D + k0 + c16 * 8);
    }
    CP_COMMIT();
}

__global__ __launch_bounds__(256, 2) void gemm_mma_kernel(
    const __half* __restrict__ Af, const __half* __restrict__ Bt,
    __half* __restrict__ C) {
    extern __shared__ char smem[];
    const uint32_t sb = smem_to_u32(smem);
    const int tid = threadIdx.x;
    const int wid = tid >> 5;
    const int lane = tid & 31;

    const int mrow0 = blockIdx.y * TILE_M;
    const int nrow0 = blockIdx.x * TILE_N;

    const int m0 = (wid & 3) * 32;   // warp m offset
    const int n0 = (wid >> 2) * 64;  // warp n offset

    float acc[2][8][4];
#pragma unroll
    for (int mt = 0; mt < 2; mt++)
#pragma unroll
        for (int nt = 0; nt < 8; nt++)
#pragma unroll
            for (int q = 0; q < 4; q++) acc[mt][nt][q] = 0.f;

    load_chunk(sb + 0 * STAGE_BYTES, Af, Bt, mrow0, nrow0, 0 * BKC, tid);
    load_chunk(sb + 1 * STAGE_BYTES, Af, Bt, mrow0, nrow0, 1 * BKC, tid);
    load_chunk(sb + 2 * STAGE_BYTES, Af, Bt, mrow0, nrow0, 2 * BKC, tid);

    const int a_rowl = lane & 15;
    const int a_half = lane >> 4;
    const int b_g = lane >> 3;
    const int b_rowl = lane & 7;

    for (int c = 0; c < N_CHUNKS; c++) {
        if (c < N_CHUNKS - 2) { CP_WAIT(2); }
        else if (c == N_CHUNKS - 2) { CP_WAIT(1); }
        else { CP_WAIT(0); }
        __syncthreads();

        const uint32_t stage = sb + (uint32_t)(c % NSTAGE) * STAGE_BYTES;
        const uint32_t aS = stage + A_OFF, bS = stage + B_OFF;

#pragma unroll
        for (int ks = 0; ks < 4; ks++) {
            uint32_t a[2][4];
#pragma unroll
            for (int mt = 0; mt < 2; mt++) {
                const uint32_t aoff = swz128((uint32_t)((m0 + mt * 16 + a_rowl) * 128 + ks * 32 + a_half * 16));
                ldsm4(a[mt], aS + aoff);
            }
            uint32_t b[8][2];
#pragma unroll
            for (int jt = 0; jt < 4; jt++) {
                const int brow = n0 + (jt * 2 + (b_g >> 1)) * 8 + b_rowl;
                const int bkb = ks * 32 + (b_g & 1) * 16;
                const uint32_t boff = swz128((uint32_t)(brow * 128 + bkb));
                uint32_t t4[4];
                ldsm4(t4, bS + boff);
                b[jt * 2][0] = t4[0]; b[jt * 2][1] = t4[1];
                b[jt * 2 + 1][0] = t4[2]; b[jt * 2 + 1][1] = t4[3];
            }
#pragma unroll
            for (int mt = 0; mt < 2; mt++)
#pragma unroll
                for (int nt = 0; nt < 8; nt++)
                    mma16816h(acc[mt][nt], a[mt], b[nt]);
        }
        __syncthreads();
        if (c + NSTAGE < N_CHUNKS)
            load_chunk(stage, Af, Bt, mrow0, nrow0, (c + NSTAGE) * BKC, tid);
    }

    // epilogue: fp16 stores
    const int er = lane >> 2;
    const int ec = (lane & 3) * 2;
#pragma unroll
    for (int mt = 0; mt < 2; mt++) {
        const int r0 = mrow0 + m0 + mt * 16 + er;
#pragma unroll
        for (int nt = 0; nt < 8; nt++) {
            const int col = nrow0 + n0 + nt * 8 + ec;
            *reinterpret_cast<__half2*>(C + (size_t)r0 * D + col) =
                __floats2half2_rn(acc[mt][nt][0], acc[mt][nt][1]);
            *reinterpret_cast<__half2*>(C + (size_t)(r0 + 8) * D + col) =
                __floats2half2_rn(acc[mt][nt][2], acc[mt][nt][3]);
        }
    }
}

// ---------------------------------------------------------------------------
// SpMM + ReLU: fp16 gather, 2 warps per row, CSR row_ptr, 4-edge unroll
// ---------------------------------------------------------------------------
__device__ __forceinline__ void fma8(float acc[8], const uint4& q, float v) {
    const __half2* hp = reinterpret_cast<const __half2*>(&q);
#pragma unroll
    for (int j = 0; j < 4; j++) {
        float2 f = __half22float2(hp[j]);
        acc[j * 2 + 0] = fmaf(v, f.x, acc[j * 2 + 0]);
        acc[j * 2 + 1] = fmaf(v, f.y, acc[j * 2 + 1]);
    }
}

__global__ __launch_bounds__(256) void spmm_relu_kernel(const int* __restrict__ row_ptr,
                                                        const int* __restrict__ cols,
                                                        const float* __restrict__ vals,
                                                        const __half* __restrict__ h,
                                                        float* __restrict__ out) {
    const int warp = threadIdx.x >> 5;
    const int lane = threadIdx.x & 31;
    const int gw = blockIdx.x * (blockDim.x >> 5) + warp;
    const int r = gw >> 1;
    if (r >= N_NODES) return;
    const int doff = (gw & 1) * 256 + lane * 8;

    const int start = __ldg(&row_ptr[r]);
    const int end = __ldg(&row_ptr[r + 1]);

    float acc[8];
#pragma unroll
    for (int j = 0; j < 8; j++) acc[j] = 0.f;

    int e = start;
    for (; e + 4 <= end; e += 4) {
        const int c0 = __ldg(&cols[e]);
        const int c1 = __ldg(&cols[e + 1]);
        const int c2 = __ldg(&cols[e + 2]);
        const int c3 = __ldg(&cols[e + 3]);
        const float v0 = __ldg(&vals[e]);
        const float v1 = __ldg(&vals[e + 1]);
        const float v2 = __ldg(&vals[e + 2]);
        const float v3 = __ldg(&vals[e + 3]);
        const uint4 q0 = *reinterpret_cast<const uint4*>(h + (size_t)c0 * D + doff);
        const uint4 q1 = *reinterpret_cast<const uint4*>(h + (size_t)c1 * D + doff);
        const uint4 q2 = *reinterpret_cast<const uint4*>(h + (size_t)c2 * D + doff);
        const uint4 q3 = *reinterpret_cast<const uint4*>(h + (size_t)c3 * D + doff);
        fma8(acc, q0, v0);
        fma8(acc, q1, v1);
        fma8(acc, q2, v2);
        fma8(acc, q3, v3);
    }
    for (; e < end; e++) {
        const int c = __ldg(&cols[e]);
        const float v = __ldg(&vals[e]);
        const uint4 q = *reinterpret_cast<const uint4*>(h + (size_t)c * D + doff);
        fma8(acc, q, v);
    }

    float4* op = reinterpret_cast<float4*>(out + (size_t)r * D + doff);
    op[0] = make_float4(fmaxf(acc[0], 0.f), fmaxf(acc[1], 0.f),
                        fmaxf(acc[2], 0.f), fmaxf(acc[3], 0.f));
    op[1] = make_float4(fmaxf(acc[4], 0.f), fmaxf(acc[5], 0.f),
                        fmaxf(acc[6], 0.f), fmaxf(acc[7], 0.f));
}

// ---------------------------------------------------------------------------
// kernel_launch
// ---------------------------------------------------------------------------
extern "C" void kernel_launch(void* const* d_in, const int* in_sizes, int n_in,
                              void* d_out, int out_size) {
    const int* adj_rows = (const int*)d_in[0];
    const int* adj_cols = (const int*)d_in[1];
    const float* adj_vals = (const float*)d_in[2];
    const float* u_f = (const float*)d_in[3];
    const float* weight = (const float*)d_in[4];
    float* out = (float*)d_out;

    __half* h;  cudaGetSymbolAddress((void**)&h, g_h);
    __half* Af; cudaGetSymbolAddress((void**)&Af, g_Af);
    __half* Bt; cudaGetSymbolAddress((void**)&Bt, g_Btf);
    int* rp;    cudaGetSymbolAddress((void**)&rp, g_rowptr);

    cudaFuncSetAttribute(gemm_mma_kernel, cudaFuncAttributeMaxDynamicSharedMemorySize, GEMM_SMEM);

    const size_t total4 = (size_t)M_PAD * D / 4;
    convertA_kernel<<<(unsigned)((total4 + 255) / 256), 256>>>(u_f, Af);
    convertW_kernel<<<dim3(D / 32, D / 32), dim3(32, 32)>>>(weight, Bt);
    build_rowptr_kernel<<<(N_EDGES + 255) / 256, 256>>>(adj_rows, rp);

    dim3 ggrid(D / TILE_N, M_PAD / TILE_M);   // (4, 391)
    gemm_mma_kernel<<<ggrid, 256, GEMM_SMEM>>>(Af, Bt, h);

    const int total_warps = N_NODES * 2;
    const int nblocks = (total_warps + 7) / 8;
    spmm_relu_kernel<<<nblocks, 256>>>(rp, adj_cols, adj_vals, h, out);
}